// round 2
// baseline (speedup 1.0000x reference)
#include <cuda_runtime.h>
#include <cuda_bf16.h>

// GruDirection3d forward wavefront:
//   out[d,y,x] = z*h_tilde + (1-z)*out[d-1,y-1,x-1],  border -> h0
//
// One CTA per (b,c) volume (192 CTAs). Sweep planes in d. Previous output
// plane lives in a double-buffered 33x33 smem tile (row 0 / col 0 pinned h0).
// Depth-4 register pipeline on the z/h_tilde plane loads (float4) hides DRAM
// latency across 4 iterations. Smem row stride 33 makes both the shifted
// scalar reads and shifted scalar writes bank-conflict-free permutations.

#define DDIM   32
#define PLANE4 256      // 32*32/4 float4 per plane
#define STRIDE 33       // smem row stride (floats)
#define TILE   (STRIDE * 33)

__global__ __launch_bounds__(256)
void gru3d_kernel(const float4* __restrict__ zv,
                  const float4* __restrict__ hv,
                  const float*  __restrict__ h0p,
                  float4*       __restrict__ ov)
{
    __shared__ float buf[2][TILE];

    const float h0 = __ldg(h0p);
    const int tid = threadIdx.x;

    // Init both buffers to h0 (interior overwritten every iter; border stays).
    #pragma unroll
    for (int i = tid; i < 2 * TILE; i += 256)
        (&buf[0][0])[i] = h0;

    const int y  = tid >> 3;    // 0..31 (row)
    const int x4 = tid & 7;     // 0..7  (float4 column group)

    const size_t base = (size_t)blockIdx.x * (DDIM * PLANE4) + (size_t)(y * 8 + x4);
    const float4* zp = zv + base;
    const float4* hp = hv + base;
    float4*       op = ov + base;

    // Prologue: planes 0..3 in flight.
    float4 zb[4], hb[4];
    #pragma unroll
    for (int s = 0; s < 4; ++s) {
        zb[s] = zp[(size_t)s * PLANE4];
        hb[s] = hp[(size_t)s * PLANE4];
    }

    __syncthreads();   // buffer init visible

    // ext[r][c] == out_prev[r-1][c-1]; this thread reads ext[y][4*x4+j],
    // writes ext[y+1][4*x4+j+1]. With STRIDE=33 both are bank permutations.
    const int rbase = y * STRIDE + 4 * x4;
    const int wbase = (y + 1) * STRIDE + 4 * x4 + 1;

    #pragma unroll
    for (int d = 0; d < DDIM; ++d) {
        const int s = d & 3;
        const float4 zc = zb[s];
        const float4 hc = hb[s];

        // Refill this pipeline stage with plane d+4 (4 iterations of cover).
        if (d + 4 < DDIM) {
            zb[s] = zp[(size_t)(d + 4) * PLANE4];
            hb[s] = hp[(size_t)(d + 4) * PLANE4];
        }

        const float* rb = &buf[(d + 1) & 1][rbase];
        float p0 = rb[0], p1 = rb[1], p2 = rb[2], p3 = rb[3];

        float4 o;
        o.x = fmaf(zc.x, hc.x - p0, p0);
        o.y = fmaf(zc.y, hc.y - p1, p1);
        o.z = fmaf(zc.z, hc.z - p2, p2);
        o.w = fmaf(zc.w, hc.w - p3, p3);

        float* wb = &buf[d & 1][wbase];
        wb[0] = o.x; wb[1] = o.y; wb[2] = o.z; wb[3] = o.w;

        op[(size_t)d * PLANE4] = o;

        __syncthreads();   // plane d writes visible before plane d+1 reads
    }
}

extern "C" void kernel_launch(void* const* d_in, const int* in_sizes, int n_in,
                              void* d_out, int out_size)
{
    const float4* z  = (const float4*)d_in[0];
    const float4* ht = (const float4*)d_in[1];
    const float*  h0 = (const float*)d_in[2];
    float4* out = (float4*)d_out;

    const int n_volumes = out_size / (DDIM * PLANE4 * 4);   // B*C = 192
    gru3d_kernel<<<n_volumes, 256>>>(z, ht, h0, out);
}